// round 9
// baseline (speedup 1.0000x reference)
#include <cuda_runtime.h>
#include <cuda_pipeline_primitives.h>

#define B_N 16
#define K_N 20
#define H_N 256
#define W_N 256
#define HW_N 65536
#define RAD 4
#define STRIP_H 64
#define PADH 72      // STRIP_H + 2*RAD (divisible by 9)
#define NSTRIP 4
#define NPART (B_N*NSTRIP)   // 64 partials per class
#define CH 16                // HW chunks in stats
#define GR 9                 // rows per async group
#define NG (PADH/GR)         // 8 groups
#define SROWS (2*GR)         // 18-row smem ring (2 groups)
#define SW 264               // padded row width in smem

typedef unsigned long long u64;
typedef unsigned int u32;

// packed f32x2 helpers (Blackwell; ptxas won't auto-fuse — PTX only)
#define FMA2(d, a, b, c) asm("fma.rn.f32x2 %0, %1, %2, %3;" : "=l"(d) : "l"(a), "l"(b), "l"(c))
#define MUL2(d, a, b)    asm("mul.rn.f32x2 %0, %1, %2;"     : "=l"(d) : "l"(a), "l"(b))
#define ADD2(d, a, b)    asm("add.rn.f32x2 %0, %1, %2;"     : "=l"(d) : "l"(a), "l"(b))
#define PACK2(d, lo, hi) asm("mov.b64 %0, {%1, %2};" : "=l"(d) : "r"(__float_as_uint(lo)), "r"(__float_as_uint(hi)))
#define UNPACK2(lo, hi, s) do { u32 _a, _b; asm("mov.b64 {%0, %1}, %2;" : "=r"(_a), "=r"(_b) : "l"(s)); lo = __uint_as_float(_a); hi = __uint_as_float(_b); } while (0)

__device__ float g_stats4[B_N * K_N * CH * 4];
__device__ float g_num[K_N * NPART];
__device__ float g_den[K_N * NPART];

// ---------------------------------------------------------------------------
// Kernel 1: per-(b,k) partial sums over an HW chunk. KG=1, all 16 LDG.128
// front-batched into registers for MLP=16.
// ---------------------------------------------------------------------------
__global__ __launch_bounds__(256) void stats_kernel(const float* __restrict__ labels,
                                                    const float* __restrict__ inputs) {
    const int k = blockIdx.x, b = blockIdx.y, ch = blockIdx.z, t = threadIdx.x;
    const int chunk = HW_N / CH;       // 4096 floats

    const float4* X0 = (const float4*)(inputs + (size_t)(b * 3 + 0) * HW_N + ch * chunk);
    const float4* X1 = (const float4*)(inputs + (size_t)(b * 3 + 1) * HW_N + ch * chunk);
    const float4* X2 = (const float4*)(inputs + (size_t)(b * 3 + 2) * HW_N + ch * chunk);
    const float4* L  = (const float4*)(labels + (size_t)(b * K_N + k) * HW_N + ch * chunk);

    // front-batch all 16 wide loads (4 iterations x 4 streams)
    float4 lv[4], v0[4], v1[4], v2[4];
    #pragma unroll
    for (int j = 0; j < 4; j++) {
        const int i = t + 256 * j;
        lv[j] = __ldg(L + i);
        v0[j] = __ldg(X0 + i);
        v1[j] = __ldg(X1 + i);
        v2[j] = __ldg(X2 + i);
    }

    float a0 = 0.f, a1 = 0.f, a2 = 0.f, a3 = 0.f;
    #pragma unroll
    for (int j = 0; j < 4; j++) {
        const float4 l = lv[j], x0 = v0[j], x1 = v1[j], x2 = v2[j];
        a0 += (l.x + l.y) + (l.z + l.w);
        a1 = fmaf(l.x, x0.x, fmaf(l.y, x0.y, fmaf(l.z, x0.z, fmaf(l.w, x0.w, a1))));
        a2 = fmaf(l.x, x1.x, fmaf(l.y, x1.y, fmaf(l.z, x1.z, fmaf(l.w, x1.w, a2))));
        a3 = fmaf(l.x, x2.x, fmaf(l.y, x2.y, fmaf(l.z, x2.z, fmaf(l.w, x2.w, a3))));
    }

    #pragma unroll
    for (int o = 16; o; o >>= 1) {
        a0 += __shfl_down_sync(0xffffffffu, a0, o);
        a1 += __shfl_down_sync(0xffffffffu, a1, o);
        a2 += __shfl_down_sync(0xffffffffu, a2, o);
        a3 += __shfl_down_sync(0xffffffffu, a3, o);
    }
    __shared__ float red[8][4];
    const int wid = t >> 5, lane = t & 31;
    if (lane == 0) { red[wid][0] = a0; red[wid][1] = a1; red[wid][2] = a2; red[wid][3] = a3; }
    __syncthreads();
    if (t < 4) {
        float v = 0.f;
        #pragma unroll
        for (int w = 0; w < 8; w++) v += red[w][t];
        g_stats4[((b * K_N + k) * CH + ch) * 4 + t] = v;
    }
}

// ---------------------------------------------------------------------------
// Kernel 2: adjoint-fused main pass, cp.async staging + packed f32x2 math.
//   num_k = sum (l*w) * blur(l),  den_k = sum w * blur(l)
// ---------------------------------------------------------------------------
__global__ __launch_bounds__(128) void main_kernel(const float* __restrict__ labels,
                                                   const float* __restrict__ inputs) {
    const int t = threadIdx.x;
    const int s = blockIdx.x;   // strip 0..3
    const int k = blockIdx.y;
    const int b = blockIdx.z;

    // g(d) = exp(-d^2 / (2*5^2)) -> literal immediates in scalar h-blur
    constexpr float G[9] = {0.72614903f, 0.83527021f, 0.92311635f, 0.98019867f, 1.0f,
                            0.98019867f, 0.92311635f, 0.83527021f, 0.72614903f};

    __shared__ float sTile[SROWS][SW];   // 18 x 264 floats
    __shared__ float sstat[4];

    if (t < 4) {
        float v = 0.f;
        #pragma unroll
        for (int ch = 0; ch < CH; ch++)
            v += g_stats4[((b * K_N + k) * CH + ch) * 4 + t];
        sstat[t] = v;
    }
    // zero the permanent horizontal pad columns (0..3 and 260..263)
    if (t < SROWS * 8) {
        const int r = t >> 3, c = t & 7;
        sTile[r][(c < 4) ? c : (SW - 8 + c)] = 0.f;
    }
    __syncthreads();

    // class_mean_c = sumX_c / (sumL + 1e-5*HW); packed negated means
    const float inv = 1.0f / (sstat[0] + 0.65536f);
    const float cm0 = sstat[1] * inv, cm1 = sstat[2] * inv, cm2 = sstat[3] * inv;
    u64 ncm0, ncm1, ncm2;
    PACK2(ncm0, -cm0, -cm0);
    PACK2(ncm1, -cm1, -cm1);
    PACK2(ncm2, -cm2, -cm2);
    // packed blur coefficients
    u64 G2[9];
    #pragma unroll
    for (int j = 0; j < 9; j++) PACK2(G2[j], G[j], G[j]);

    const float* lab = labels + (size_t)(b * K_N + k) * HW_N;
    const float* xp0 = inputs + (size_t)(b * 3) * HW_N;
    const float* xp1 = xp0 + HW_N;
    const float* xp2 = xp1 + HW_N;

    const int row0 = s * STRIP_H - RAD;   // global row of padded row 0
    const int oc0 = 2 * t;                // this thread's two output columns

    // --- stage one 9-row group: 9 rows x 64 float4 chunks ---
    auto stage = [&](int g) {
        for (int task = t; task < GR * 64; task += 128) {
            const int r  = task >> 6;
            const int c4 = task & 63;
            const int pr = g * GR + r;
            const int gr = row0 + pr;
            float* dst = &sTile[pr % SROWS][4 + c4 * 4];
            if ((unsigned)gr < (unsigned)H_N) {
                __pipeline_memcpy_async(dst, lab + gr * W_N + c4 * 4, 16);
            } else {
                *(float4*)dst = make_float4(0.f, 0.f, 0.f, 0.f);
            }
        }
    };

    stage(0); __pipeline_commit();
    stage(1); __pipeline_commit();

    u64 rb[9];              // ring: packed h-blurred label pairs
    u64 ra[9];              // ring: packed raw center label pairs
    u64 num2, den2;
    PACK2(num2, 0.f, 0.f);
    PACK2(den2, 0.f, 0.f);

    for (int g = 0; g < NG; g++) {
        __pipeline_wait_prior(1);
        __syncthreads();          // group g resident

        #pragma unroll
        for (int u = 0; u < 9; u++) {
            const int pr = g * GR + u;
            const float* srow = &sTile[pr % SROWS][oc0];  // pad col oc0 = global col oc0-4

            // --- 10-value horizontal window: 5 LDS.64 ---
            float v[10];
            u64 center;
            #pragma unroll
            for (int i = 0; i < 5; i++) {
                const float2 a = *(const float2*)(srow + 2 * i);
                v[2 * i] = a.x; v[2 * i + 1] = a.y;
                if (i == 2) PACK2(center, a.x, a.y);
            }

            // --- horizontal 9-tap (scalar, FFMA-imm) ---
            float h0 = v[0] * G[0], h1 = v[1] * G[0];
            #pragma unroll
            for (int j = 1; j < 9; j++) {
                h0 = fmaf(v[j],     G[j], h0);
                h1 = fmaf(v[j + 1], G[j], h1);
            }
            PACK2(rb[u], h0, h1);              // slot pr%9 == u
            ra[u] = center;

            // --- vertical 9-tap (packed) completes row gor = s*64 + pr - 8 ---
            if (pr >= 8) {
                u64 Bv;
                {
                    const int s0 = (u + 1) % 9;
                    MUL2(Bv, rb[s0], G2[0]);
                }
                #pragma unroll
                for (int j = 1; j < 9; j++) {
                    const int slot = (u + 1 + j) % 9;   // static
                    FMA2(Bv, rb[slot], G2[j], Bv);
                }
                const u64 lc = ra[(u + 5) % 9];         // raw labels at center row

                const int gor = s * STRIP_H + pr - 8;
                const int idx = gor * W_N + oc0;
                const u64 xu0 = __ldg((const u64*)(xp0 + idx));   // packed pair
                const u64 xu1 = __ldg((const u64*)(xp1 + idx));
                const u64 xu2 = __ldg((const u64*)(xp2 + idx));

                // packed diff^2 accumulation
                u64 a0, a1, a2, dd;
                ADD2(a0, xu0, ncm0);
                ADD2(a1, xu1, ncm1);
                ADD2(a2, xu2, ncm2);
                MUL2(dd, a2, a2);
                FMA2(dd, a1, a1, dd);
                FMA2(dd, a0, a0, dd);
                u64 s2;
                MUL2(s2, dd, dd);               // (d^2), want exp(-d^2)

                float s0f, s1f;
                UNPACK2(s0f, s1f, s2);
                const float w0 = __expf(-s0f);
                const float w1 = __expf(-s1f);
                u64 wp;
                PACK2(wp, w0, w1);

                u64 lw;
                MUL2(lw, lc, wp);
                FMA2(num2, lw, Bv, num2);
                FMA2(den2, wp, Bv, den2);
            }
        }

        __syncthreads();          // all threads done reading group g
        if (g + 2 < NG) { stage(g + 2); }
        __pipeline_commit();
    }

    float nx, ny, dx, dy;
    UNPACK2(nx, ny, num2);
    UNPACK2(dx, dy, den2);
    float numAcc = nx + ny;
    float denAcc = dx + dy;

    // --- deterministic block reduction ---
    #pragma unroll
    for (int o = 16; o; o >>= 1) {
        numAcc += __shfl_down_sync(0xffffffffu, numAcc, o);
        denAcc += __shfl_down_sync(0xffffffffu, denAcc, o);
    }
    __shared__ float rn[4], rd[4];
    if ((t & 31) == 0) { rn[t >> 5] = numAcc; rd[t >> 5] = denAcc; }
    __syncthreads();
    if (t == 0) {
        const float n = (rn[0] + rn[1]) + (rn[2] + rn[3]);
        const float d = (rd[0] + rd[1]) + (rd[2] + rd[3]);
        const int idx = (k * B_N + b) * NSTRIP + s;
        g_num[idx] = n;
        g_den[idx] = d;
    }
}

// ---------------------------------------------------------------------------
// Kernel 3: final deterministic reduction -> scalar loss
// ---------------------------------------------------------------------------
__global__ void finish_kernel(float* __restrict__ out) {
    __shared__ float sv[K_N];
    const int t = threadIdx.x;
    if (t < K_N) {
        float n = 0.f, d = 0.f;
        for (int i = 0; i < NPART; i++) {
            n += g_num[t * NPART + i];
            d += g_den[t * NPART + i];
        }
        sv[t] = fabsf(n / (d + 1e-6f));
    }
    __syncthreads();
    if (t == 0) {
        float loss = 0.f;
        for (int i = 0; i < K_N; i++) loss += sv[i];
        out[0] = (float)K_N - loss;
    }
}

// ---------------------------------------------------------------------------
extern "C" void kernel_launch(void* const* d_in, const int* in_sizes, int n_in,
                              void* d_out, int out_size) {
    (void)n_in; (void)out_size;
    const float* labels;
    const float* inputs;
    if (in_sizes[0] == B_N * K_N * HW_N) {
        labels = (const float*)d_in[0];
        inputs = (const float*)d_in[1];
    } else {
        labels = (const float*)d_in[1];
        inputs = (const float*)d_in[0];
    }
    float* out = (float*)d_out;

    stats_kernel<<<dim3(K_N, B_N, CH), 256>>>(labels, inputs);
    main_kernel<<<dim3(NSTRIP, K_N, B_N), 128>>>(labels, inputs);
    finish_kernel<<<1, 32>>>(out);
}